// round 9
// baseline (speedup 1.0000x reference)
#include <cuda_runtime.h>
#include <cstdint>

// GVCNN group pooling collapsed to out[n,c] = sum_v coef[n,gid[n,v]] * RPs[n,v,c].
//
// TMA/bulk-async + mbarrier pipeline: each sample's tile is a contiguous
// 12KB block in gmem -> 1D cp.async.bulk into a 3-stage smem ring. Thread 0
// refills stage s with sample i+3 right after the post-epilogue syncthreads
// frees it (producer==thread0 => program order replaces empty barriers).
// The async copy engine keeps DRAM busy regardless of the compute tail that
// capped the register-tile designs (R6-R8) at ~60-69% DRAM.
//
// Compute per sample (from smem): 4 warps x 3 views, 15-SHFL butterflies,
// warp-parallel binning (match_any+popc) in warp 0, 64-thread epilogue
// re-reading the smem tile. No register tile -> ~45 regs; occupancy bound
// by smem only (37KB -> 6 CTAs = 24 warps/SM).

#define NV   12
#define SPB  8                    // samples per block
#define NST  3                    // pipeline stages
#define TILE_BYTES (NV * 256 * 4) // 12288, contiguous per sample
#define EPSF 1e-6f

__device__ __forceinline__ uint32_t smem_u32(const void* p) {
    return (uint32_t)__cvta_generic_to_shared(p);
}

__device__ __forceinline__ void mbar_init(uint32_t mbar, uint32_t cnt) {
    asm volatile("mbarrier.init.shared.b64 [%0], %1;" :: "r"(mbar), "r"(cnt) : "memory");
}

__device__ __forceinline__ void mbar_expect_tx(uint32_t mbar, uint32_t bytes) {
    asm volatile("mbarrier.arrive.expect_tx.shared.b64 _, [%0], %1;"
                 :: "r"(mbar), "r"(bytes) : "memory");
}

__device__ __forceinline__ void bulk_g2s(uint32_t dst, const void* src,
                                         uint32_t bytes, uint32_t mbar) {
    asm volatile(
        "cp.async.bulk.shared::cluster.global.mbarrier::complete_tx::bytes "
        "[%0], [%1], %2, [%3];"
        :: "r"(dst), "l"(src), "r"(bytes), "r"(mbar) : "memory");
}

__device__ __forceinline__ void mbar_wait(uint32_t mbar, uint32_t parity) {
    asm volatile(
        "{\n\t"
        ".reg .pred P;\n\t"
        "WL_%=:\n\t"
        "mbarrier.try_wait.parity.acquire.cta.shared::cta.b64 P, [%0], %1, 0x989680;\n\t"
        "@P bra.uni WD_%=;\n\t"
        "bra.uni WL_%=;\n\t"
        "WD_%=:\n\t"
        "}"
        :: "r"(mbar), "r"(parity) : "memory");
}

__global__ __launch_bounds__(128) void gvcnn_kernel(
    const float4* __restrict__ RPs4,   // [N, 12, 64] float4
    const float4* __restrict__ w4p,    // [64] float4
    const float*  __restrict__ b,
    float4*       __restrict__ out4)   // [N, 64] float4
{
    __shared__ __align__(16) float4 s_tile[NST][NV * 64];   // 3 x 12KB
    __shared__ __align__(8)  unsigned long long s_mbar[NST];
    __shared__ float s_y[NV];
    __shared__ float s_coef[NV];

    const int tid  = threadIdx.x;
    const int lane = tid & 31;
    const int wid  = tid >> 5;                // 0..3
    const size_t n0 = (size_t)blockIdx.x * SPB;

    const float4 wa = w4p[lane];
    const float4 wb = w4p[lane + 32];
    const float  bb = b[0];

    if (tid == 0) {
#pragma unroll
        for (int s = 0; s < NST; s++) mbar_init(smem_u32(&s_mbar[s]), 1);
    }
    __syncthreads();

    // ---- prologue: fill all stages ----
    if (tid == 0) {
#pragma unroll
        for (int k = 0; k < NST; k++) {
            const uint32_t mb = smem_u32(&s_mbar[k]);
            mbar_expect_tx(mb, TILE_BYTES);
            bulk_g2s(smem_u32(&s_tile[k][0]),
                     RPs4 + (n0 + k) * (NV * 64), TILE_BYTES, mb);
        }
    }

    for (int i = 0; i < SPB; i++) {
        const int s  = i % NST;
        const uint32_t ph = (uint32_t)((i / NST) & 1);
        mbar_wait(smem_u32(&s_mbar[s]), ph);

        const float4* tile = s_tile[s];
        const size_t n = n0 + i;

        // ---- dot phase: warp w owns views 3w..3w+2 ----
        {
            const int v0 = wid * 3;
            float p[3];
#pragma unroll
            for (int j = 0; j < 3; j++) {
                const float4 t0 = tile[(v0 + j) * 64 + lane];
                const float4 t1 = tile[(v0 + j) * 64 + 32 + lane];
                p[j] = t0.x * wa.x + t0.y * wa.y + t0.z * wa.z + t0.w * wa.w
                     + t1.x * wb.x + t1.y * wb.y + t1.z * wb.z + t1.w * wb.w;
            }
#pragma unroll
            for (int off = 16; off > 0; off >>= 1) {
#pragma unroll
                for (int j = 0; j < 3; j++)
                    p[j] += __shfl_xor_sync(0xffffffffu, p[j], off);
            }
            if (lane == 0) {
#pragma unroll
                for (int j = 0; j < 3; j++) s_y[v0 + j] = p[j];
            }
        }
        __syncthreads();

        // ---- warp-parallel binning, once per sample (warp 0) ----
        if (wid == 0) {
            const float y  = s_y[lane < NV ? lane : 0];
            const float x  = fabsf(y + bb) + EPSF;
            const float sc = x / (1.0f + x);                  // == sigmoid(log(x))
            const int  gid = min((int)(sc * 10.0f), 9) >> 1;  // 0..4

            const unsigned mask = __match_any_sync(0xffffffffu, gid) & 0xFFFu;
            const int      gszI = __popc(mask);
            const float    gszF = (float)(gszI | (gszI == 0));
            const float    val  = ceilf(sc * gszF);

            float numer = 0.f;
#pragma unroll
            for (int u = 0; u < NV; u++) {
                const float vu = __shfl_sync(0xffffffffu, val, u);
                if ((mask >> u) & 1u) numer += vu;
            }
            const float gs = numer / (gszF + EPSF);           // group_score

            float t = (lane < NV) ? gs / gszF : 0.f;
#pragma unroll
            for (int off = 16; off > 0; off >>= 1)
                t += __shfl_xor_sync(0xffffffffu, t, off);

            const float coef = gs / (gszF + EPSF) * (1.0f / (t + EPSF));
            if (lane < NV) s_coef[lane] = coef;
        }
        __syncthreads();

        // ---- epilogue: threads 0..63, chunk u, all 12 views from smem ----
        if (tid < 64) {
            float cf[NV];
#pragma unroll
            for (int v = 0; v < NV; v++) cf[v] = s_coef[v];
            float4 acc = make_float4(0.f, 0.f, 0.f, 0.f);
#pragma unroll
            for (int v = 0; v < NV; v++) {
                const float4 t = tile[v * 64 + tid];
                acc.x += cf[v] * t.x;  acc.y += cf[v] * t.y;
                acc.z += cf[v] * t.z;  acc.w += cf[v] * t.w;
            }
            out4[n * 64 + tid] = acc;
        }
        __syncthreads();   // stage s fully consumed

        // ---- refill stage s with sample i+NST ----
        if (tid == 0 && i + NST < SPB) {
            const uint32_t mb = smem_u32(&s_mbar[s]);
            mbar_expect_tx(mb, TILE_BYTES);
            bulk_g2s(smem_u32(&s_tile[s][0]),
                     RPs4 + (n0 + i + NST) * (NV * 64), TILE_BYTES, mb);
        }
    }
}

extern "C" void kernel_launch(void* const* d_in, const int* in_sizes, int n_in,
                              void* d_out, int out_size)
{
    const float4* RPs4 = (const float4*)d_in[0];   // [8192,12,256] f32
    const float4* w4p  = (const float4*)d_in[1];   // [256] f32
    const float*  b    = (const float*)d_in[2];    // [1] f32
    float4* out4       = (float4*)d_out;           // [8192,256] f32

    const int n = in_sizes[0] / (NV * 256);        // 8192
    gvcnn_kernel<<<n / SPB, 128>>>(RPs4, w4p, b, out4);
}

// round 10
// speedup vs baseline: 1.3067x; 1.3067x over previous
#include <cuda_runtime.h>

// GVCNN group pooling collapsed to out[n,c] = sum_v coef[n,gid[n,v]] * RPs[n,v,c].
//
// ONE WARP PER SAMPLE, zero smem, zero barriers (R2 structure), with the two
// R2 cost drivers removed:
//  - transpose-reduce (send-the-half-you-don't-keep): y[v] lands IN lane v
//    with 27 SHFLs total (vs 60-SHFL full butterfly),
//  - warp-parallel binning (match_any+popc histogram, shfl-gather numerator)
//    computed once, lane v owning view v; coef broadcast by 12 shfls.
// Register tile: 24 float4 (whole sample) loaded with batched coalesced
// LDG.128, read from HBM exactly once, reused in the epilogue.

#define NV 12
#define EPSF 1e-6f

__global__ __launch_bounds__(64, 8) void gvcnn_kernel(
    const float4* __restrict__ RPs4,   // [N, 12, 64] float4
    const float4* __restrict__ w4p,    // [64] float4
    const float*  __restrict__ b,
    float4*       __restrict__ out4)   // [N, 64] float4
{
    const int lane  = threadIdx.x & 31;
    const size_t n  = (size_t)blockIdx.x * 2 + (threadIdx.x >> 5);

    // ---- batched loads: 24 independent coalesced LDG.128, nothing between ----
    const float4* base = RPs4 + n * (NV * 64) + lane;
    float4 r0[NV], r1[NV];
#pragma unroll
    for (int v = 0; v < NV; v++) {
        r0[v] = base[v * 64];
        r1[v] = base[v * 64 + 32];
    }

    const float4 wa = w4p[lane];
    const float4 wb = w4p[lane + 32];
    const float  bb = b[0];

    // ---- 12 dot partials ----
    float p[NV];
#pragma unroll
    for (int v = 0; v < NV; v++) {
        p[v] = r0[v].x * wa.x + r0[v].y * wa.y + r0[v].z * wa.z + r0[v].w * wa.w
             + r1[v].x * wb.x + r1[v].y * wb.y + r1[v].z * wb.z + r1[v].w * wb.w;
    }

    // ---- transpose-reduce: y[v] ends in lane v (27 SHFLs) ----
    // step 16: plain butterfly across halves (lanes 16..31 mirror 0..15)
#pragma unroll
    for (int i = 0; i < NV; i++)
        p[i] += __shfl_xor_sync(0xffffffffu, p[i], 16);

    const bool b8 = (lane & 8) != 0;
    const bool b4 = (lane & 4) != 0;
    const bool b2 = (lane & 2) != 0;
    const bool b1 = (lane & 1) != 0;

    float q8[8];
#pragma unroll
    for (int i = 0; i < 8; i++) {
        const float hiv  = (i + 8 < NV) ? p[i + 8] : 0.f;
        const float send = b8 ? p[i] : hiv;
        const float recv = __shfl_xor_sync(0xffffffffu, send, 8);
        q8[i] = (b8 ? hiv : p[i]) + recv;
    }
    float q4[4];
#pragma unroll
    for (int i = 0; i < 4; i++) {
        const float send = b4 ? q8[i] : q8[i + 4];
        const float recv = __shfl_xor_sync(0xffffffffu, send, 4);
        q4[i] = (b4 ? q8[i + 4] : q8[i]) + recv;
    }
    float q2[2];
#pragma unroll
    for (int i = 0; i < 2; i++) {
        const float send = b2 ? q4[i] : q4[i + 2];
        const float recv = __shfl_xor_sync(0xffffffffu, send, 2);
        q2[i] = (b2 ? q4[i + 2] : q4[i]) + recv;
    }
    float y;
    {
        const float send = b1 ? q2[0] : q2[1];
        const float recv = __shfl_xor_sync(0xffffffffu, send, 1);
        y = (b1 ? q2[1] : q2[0]) + recv;
    }
    // lane l (l = 0..11) now holds y[l]; lanes 12..15 hold 0-sums, 16..31 mirror.

    // ---- warp-parallel binning (lane v owns view v) ----
    const float x  = fabsf(y + bb) + EPSF;
    const float s  = x / (1.0f + x);                 // == sigmoid(log(x))
    const int  gid = min((int)(s * 10.0f), 9) >> 1;  // 0..4

    const unsigned mask = __match_any_sync(0xffffffffu, gid) & 0xFFFu;
    const int      gszI = __popc(mask);
    const float    gszF = (float)(gszI | (gszI == 0));
    const float    val  = ceilf(s * gszF);

    float numer = 0.f;
#pragma unroll
    for (int u = 0; u < NV; u++) {
        const float vu = __shfl_sync(0xffffffffu, val, u);
        if ((mask >> u) & 1u) numer += vu;
    }
    const float gs = numer / (gszF + EPSF);          // reference group_score

    // total = sum over bins of gs == sum over views of gs/gsize
    float t = (lane < NV) ? gs / gszF : 0.f;
#pragma unroll
    for (int off = 16; off > 0; off >>= 1)
        t += __shfl_xor_sync(0xffffffffu, t, off);

    const float coef = gs / (gszF + EPSF) * (1.0f / (t + EPSF));

    // ---- broadcast the 12 coefficients to all lanes ----
    float cf[NV];
#pragma unroll
    for (int v = 0; v < NV; v++)
        cf[v] = __shfl_sync(0xffffffffu, coef, v);

    // ---- epilogue: weighted sum straight from the register tile ----
    float4 a0 = make_float4(0.f, 0.f, 0.f, 0.f);
    float4 a1 = make_float4(0.f, 0.f, 0.f, 0.f);
#pragma unroll
    for (int v = 0; v < NV; v++) {
        a0.x += cf[v] * r0[v].x;  a0.y += cf[v] * r0[v].y;
        a0.z += cf[v] * r0[v].z;  a0.w += cf[v] * r0[v].w;
        a1.x += cf[v] * r1[v].x;  a1.y += cf[v] * r1[v].y;
        a1.z += cf[v] * r1[v].z;  a1.w += cf[v] * r1[v].w;
    }
    out4[n * 64 + lane]      = a0;
    out4[n * 64 + 32 + lane] = a1;
}

extern "C" void kernel_launch(void* const* d_in, const int* in_sizes, int n_in,
                              void* d_out, int out_size)
{
    const float4* RPs4 = (const float4*)d_in[0];   // [8192,12,256] f32
    const float4* w4p  = (const float4*)d_in[1];   // [256] f32
    const float*  b    = (const float*)d_in[2];    // [1] f32
    float4* out4       = (float4*)d_out;           // [8192,256] f32

    const int n = in_sizes[0] / (NV * 256);        // 8192
    gvcnn_kernel<<<n / 2, 64>>>(RPs4, w4p, b, out4);
}

// round 11
// speedup vs baseline: 1.3243x; 1.0135x over previous
#include <cuda_runtime.h>

// GVCNN group pooling collapsed to out[n,c] = sum_v coef[n,gid[n,v]] * RPs[n,v,c].
//
// One 64-thread block per sample, split BY CHANNEL: warp h owns float4
// chunks {32h + lane} (half the channels) of ALL 12 views -> 12-float4
// register tile (48 regs, like R6) => 12 CTAs = 24 warps/SM, but with
// R10's short tail: 27-SHFL transpose-reduce puts partial y[v] in lane v,
// ONE __syncthreads exchanges the two channel-half partials, then BOTH
// warps redundantly run the cheap warp-parallel binning (match_any+popc)
// and finish their own channels from their own registers. 1 barrier total.

#define NV 12
#define EPSF 1e-6f

__global__ __launch_bounds__(64, 12) void gvcnn_kernel(
    const float4* __restrict__ RPs4,   // [N, 12, 64] float4
    const float4* __restrict__ w4p,    // [64] float4
    const float*  __restrict__ b,
    float4*       __restrict__ out4)   // [N, 64] float4
{
    const int lane = threadIdx.x & 31;
    const int half = threadIdx.x >> 5;           // warp 0: chunks 0..31, warp 1: 32..63
    const size_t n = blockIdx.x;
    const int u    = half * 32 + lane;           // owned float4 chunk

    __shared__ float s_y[2][NV];

    // ---- batched loads: 12 independent coalesced LDG.128, nothing between ----
    const float4* base = RPs4 + n * (NV * 64) + u;
    float4 r[NV];
#pragma unroll
    for (int v = 0; v < NV; v++) r[v] = base[v * 64];

    const float4 wv = w4p[u];
    const float  bb = b[0];

    // ---- 12 dot partials over this warp's 128 channels ----
    float p[NV];
#pragma unroll
    for (int v = 0; v < NV; v++)
        p[v] = r[v].x * wv.x + r[v].y * wv.y + r[v].z * wv.z + r[v].w * wv.w;

    // ---- transpose-reduce: partial y[v] lands in lane v (27 SHFLs) ----
#pragma unroll
    for (int i = 0; i < NV; i++)
        p[i] += __shfl_xor_sync(0xffffffffu, p[i], 16);

    const bool b8 = (lane & 8) != 0;
    const bool b4 = (lane & 4) != 0;
    const bool b2 = (lane & 2) != 0;
    const bool b1 = (lane & 1) != 0;

    float q8[8];
#pragma unroll
    for (int i = 0; i < 8; i++) {
        const float hiv  = (i + 8 < NV) ? p[i + 8] : 0.f;
        const float send = b8 ? p[i] : hiv;
        const float recv = __shfl_xor_sync(0xffffffffu, send, 8);
        q8[i] = (b8 ? hiv : p[i]) + recv;
    }
    float q4[4];
#pragma unroll
    for (int i = 0; i < 4; i++) {
        const float send = b4 ? q8[i] : q8[i + 4];
        const float recv = __shfl_xor_sync(0xffffffffu, send, 4);
        q4[i] = (b4 ? q8[i + 4] : q8[i]) + recv;
    }
    float q2[2];
#pragma unroll
    for (int i = 0; i < 2; i++) {
        const float send = b2 ? q4[i] : q4[i + 2];
        const float recv = __shfl_xor_sync(0xffffffffu, send, 2);
        q2[i] = (b2 ? q4[i + 2] : q4[i]) + recv;
    }
    float yh;
    {
        const float send = b1 ? q2[0] : q2[1];
        const float recv = __shfl_xor_sync(0xffffffffu, send, 1);
        yh = (b1 ? q2[1] : q2[0]) + recv;
    }
    // lane v (v<12) holds this warp's channel-half partial of y[v].

    if (lane < NV) s_y[half][lane] = yh;
    __syncthreads();                             // the ONLY barrier

    // ---- warp-parallel binning, redundantly in BOTH warps (lane v owns view v) ----
    const int vl = (lane < NV) ? lane : 0;
    const float y = s_y[0][vl] + s_y[1][vl];

    const float x  = fabsf(y + bb) + EPSF;
    const float s  = x / (1.0f + x);                 // == sigmoid(log(x))
    const int  gid = min((int)(s * 10.0f), 9) >> 1;  // 0..4

    const unsigned mask = __match_any_sync(0xffffffffu, gid) & 0xFFFu;
    const int      gszI = __popc(mask);
    const float    gszF = (float)(gszI | (gszI == 0));
    const float    val  = ceilf(s * gszF);

    float numer = 0.f;
#pragma unroll
    for (int uu = 0; uu < NV; uu++) {
        const float vu = __shfl_sync(0xffffffffu, val, uu);
        if ((mask >> uu) & 1u) numer += vu;
    }
    const float gs = numer / (gszF + EPSF);          // reference group_score

    // total = sum over bins of gs == sum over views of gs/gsize
    float t = (lane < NV) ? gs / gszF : 0.f;
#pragma unroll
    for (int off = 16; off > 0; off >>= 1)
        t += __shfl_xor_sync(0xffffffffu, t, off);

    const float coef = gs / (gszF + EPSF) * (1.0f / (t + EPSF));

    // ---- broadcast the 12 coefficients, then warp-independent epilogue ----
    float cf[NV];
#pragma unroll
    for (int v = 0; v < NV; v++)
        cf[v] = __shfl_sync(0xffffffffu, coef, v);

    float4 acc = make_float4(0.f, 0.f, 0.f, 0.f);
#pragma unroll
    for (int v = 0; v < NV; v++) {
        acc.x += cf[v] * r[v].x;  acc.y += cf[v] * r[v].y;
        acc.z += cf[v] * r[v].z;  acc.w += cf[v] * r[v].w;
    }
    out4[n * 64 + u] = acc;
}

extern "C" void kernel_launch(void* const* d_in, const int* in_sizes, int n_in,
                              void* d_out, int out_size)
{
    const float4* RPs4 = (const float4*)d_in[0];   // [8192,12,256] f32
    const float4* w4p  = (const float4*)d_in[1];   // [256] f32
    const float*  b    = (const float*)d_in[2];    // [1] f32
    float4* out4       = (float4*)d_out;           // [8192,256] f32

    const int n = in_sizes[0] / (NV * 256);        // 8192
    gvcnn_kernel<<<n, 64>>>(RPs4, w4p, b, out4);
}